// round 16
// baseline (speedup 1.0000x reference)
#include <cuda_runtime.h>
#include <math.h>

// Chamfer, N=M=16384, D=3 — EXACT grid nearest-neighbor (O(N) not O(N^2)).
// 32^3 cells over [-4.8,4.8]^3 (s=0.3). Ring search with lower bound (r*s)^2.
// Clamped outliers remain exact (they are farther than their cell's bound).
// Kernels: hist -> scan -> scatter -> query -> finalize. g_cnt is zero-init
// and restored to zero by scatter's atomicSub => graph-replay idempotent.

#define G     32
#define NC    (G*G*G)                 // 32768
#define BOUND 4.8f
#define CS    (2.0f*BOUND/(float)G)   // 0.3
#define MAXN  16384
#define HTPB  256
#define QTPB  256
#define QWPB  (QTPB/32)               // 8 warps/block
#define MAXQ  (2*MAXN)
#define QGRID ((MAXQ + QWPB - 1)/QWPB)// 4096
#define STPB  1024
#define CPS   (NC/STPB)               // 32 cells per scan thread

__device__ unsigned g_cnt[2][NC];     // zero at load; scatter restores zeros
__device__ unsigned g_off[2][NC+1];
__device__ float4   g_pts[2][MAXN];
__device__ float    g_bsum[QGRID];

__device__ __forceinline__ int cellco(float x) {
    int c = __float2int_rd((x + BOUND) * (1.0f/CS));
    return min(max(c, 0), G-1);
}

__global__ void hist_kernel(const float* __restrict__ p1, int n1,
                            const float* __restrict__ p2, int n2) {
    int i = blockIdx.x * blockDim.x + threadIdx.x;
    if (i >= n1 + n2) return;
    const float* p; int s, idx;
    if (i < n1) { p = p1; s = 0; idx = i; } else { p = p2; s = 1; idx = i - n1; }
    float x = p[3*idx], y = p[3*idx+1], z = p[3*idx+2];
    int c = (cellco(z)*G + cellco(y))*G + cellco(x);
    atomicAdd(&g_cnt[s][c], 1u);
}

__global__ void __launch_bounds__(STPB) scan_kernel() {
    const int s = blockIdx.x;
    const int tid = threadIdx.x, lane = tid & 31, wid = tid >> 5;
    __shared__ unsigned wsum[32];
    unsigned tsum = 0;
    #pragma unroll
    for (int k = 0; k < CPS; k++) tsum += g_cnt[s][tid*CPS + k];
    unsigned v = tsum;
    #pragma unroll
    for (int o = 1; o < 32; o <<= 1) {
        unsigned t = __shfl_up_sync(0xffffffffu, v, o);
        if (lane >= o) v += t;
    }
    if (lane == 31) wsum[wid] = v;
    __syncthreads();
    if (wid == 0) {
        unsigned w = wsum[lane];
        #pragma unroll
        for (int o = 1; o < 32; o <<= 1) {
            unsigned t = __shfl_up_sync(0xffffffffu, w, o);
            if (lane >= o) w += t;
        }
        wsum[lane] = w;
    }
    __syncthreads();
    unsigned run = v - tsum + (wid > 0 ? wsum[wid-1] : 0u);
    #pragma unroll
    for (int k = 0; k < CPS; k++) {
        unsigned c = g_cnt[s][tid*CPS + k];
        g_off[s][tid*CPS + k] = run;
        run += c;
    }
    if (tid == STPB-1) g_off[s][NC] = run;
}

__global__ void scatter_kernel(const float* __restrict__ p1, int n1,
                               const float* __restrict__ p2, int n2) {
    int i = blockIdx.x * blockDim.x + threadIdx.x;
    if (i >= n1 + n2) return;
    const float* p; int s, idx;
    if (i < n1) { p = p1; s = 0; idx = i; } else { p = p2; s = 1; idx = i - n1; }
    float x = p[3*idx], y = p[3*idx+1], z = p[3*idx+2];
    int c = (cellco(z)*G + cellco(y))*G + cellco(x);
    unsigned t = atomicSub(&g_cnt[s][c], 1u);   // leaves cnt at 0 for next replay
    g_pts[s][g_off[s][c] + t - 1u] = make_float4(x, y, z, 0.0f);
}

__global__ void __launch_bounds__(QTPB)
query_kernel(const float* __restrict__ p1, int n1,
             const float* __restrict__ p2, int n2) {
    __shared__ float swsum[QWPB];
    const int lane = threadIdx.x & 31, wid = threadIdx.x >> 5;
    const int gw = blockIdx.x * QWPB + wid;
    const int total = n1 + n2;
    float res = 0.0f;
    if (gw < total) {
        const float* q; int s, idx;
        if (gw < n1) { q = p1; s = 1; idx = gw; }       // p1 queries vs p2 grid
        else         { q = p2; s = 0; idx = gw - n1; }  // p2 queries vs p1 grid
        const float qx = q[3*idx], qy = q[3*idx+1], qz = q[3*idx+2];
        const int cx = cellco(qx), cy = cellco(qy), cz = cellco(qz);
        const unsigned* __restrict__ off = g_off[s];
        const float4*   __restrict__ pts = g_pts[s];
        float best = __uint_as_float(0x7F800000u);
        int r = 1;
        for (;;) {
            const int zlo = max(cz-r, 0), zhi = min(cz+r, G-1);
            const int ylo = max(cy-r, 0), yhi = min(cy+r, G-1);
            const int xlo = max(cx-r, 0), xhi = min(cx+r, G-1);
            const int ny = yhi - ylo + 1;
            const int nrows = (zhi - zlo + 1) * ny;
            for (int rb = 0; rb < nrows; rb += 32) {
                int rowid = rb + lane;
                unsigned lo = 0, hi = 0;
                if (rowid < nrows) {
                    int zi = rowid / ny;
                    int yi = rowid - zi * ny;
                    int rowb = ((zlo + zi)*G + (ylo + yi))*G;
                    lo = off[rowb + xlo];
                    hi = off[rowb + xhi + 1];
                }
                unsigned act = __ballot_sync(0xffffffffu, hi > lo);
                while (act) {
                    int src = __ffs(act) - 1;
                    act &= act - 1u;
                    unsigned rlo = __shfl_sync(0xffffffffu, lo, src);
                    unsigned rhi = __shfl_sync(0xffffffffu, hi, src);
                    for (unsigned k = rlo + lane; k < rhi; k += 32) {
                        float4 pt = pts[k];
                        float dx = pt.x - qx, dy = pt.y - qy, dz = pt.z - qz;
                        float d2 = fmaf(dx, dx, fmaf(dy, dy, dz*dz));
                        best = fminf(best, d2);
                    }
                }
            }
            float b = best;
            b = fminf(b, __shfl_xor_sync(0xffffffffu, b, 16));
            b = fminf(b, __shfl_xor_sync(0xffffffffu, b, 8));
            b = fminf(b, __shfl_xor_sync(0xffffffffu, b, 4));
            b = fminf(b, __shfl_xor_sync(0xffffffffu, b, 2));
            b = fminf(b, __shfl_xor_sync(0xffffffffu, b, 1));
            float bnd = (float)r * CS;
            if (bnd*bnd >= b || r >= G) { best = b; break; }
            r++;
        }
        res = sqrtf(best);
    }
    if (lane == 0) swsum[wid] = (gw < total) ? res : 0.0f;
    __syncthreads();
    if (wid == 0) {
        float v = (lane < QWPB) ? swsum[lane] : 0.0f;
        v += __shfl_xor_sync(0xffffffffu, v, 4);
        v += __shfl_xor_sync(0xffffffffu, v, 2);
        v += __shfl_xor_sync(0xffffffffu, v, 1);
        if (lane == 0) g_bsum[blockIdx.x] = v;
    }
}

__global__ void __launch_bounds__(512) finalize_kernel(float* __restrict__ out) {
    __shared__ float ss[16];
    int tid = threadIdx.x, lane = tid & 31, wid = tid >> 5;
    float v = 0.0f;
    for (int k = tid; k < QGRID; k += 512) v += g_bsum[k];
    #pragma unroll
    for (int o = 16; o; o >>= 1) v += __shfl_down_sync(0xffffffffu, v, o);
    if (lane == 0) ss[wid] = v;
    __syncthreads();
    if (wid == 0) {
        float w = (lane < 16) ? ss[lane] : 0.0f;
        #pragma unroll
        for (int o = 8; o; o >>= 1) w += __shfl_down_sync(0xffffffffu, w, o);
        if (lane == 0) out[0] = w;
    }
}

extern "C" void kernel_launch(void* const* d_in, const int* in_sizes, int n_in,
                              void* d_out, int out_size) {
    const float* p1 = (const float*)d_in[0];
    const float* p2 = (const float*)d_in[1];
    int n1 = in_sizes[0] / 3;
    int n2 = in_sizes[1] / 3;
    float* out = (float*)d_out;

    int hb = (n1 + n2 + HTPB - 1) / HTPB;
    hist_kernel   <<<hb, HTPB>>>(p1, n1, p2, n2);
    scan_kernel   <<<2, STPB>>>();
    scatter_kernel<<<hb, HTPB>>>(p1, n1, p2, n2);
    query_kernel  <<<QGRID, QTPB>>>(p1, n1, p2, n2);   // launch #4 -> ncu capture
    finalize_kernel<<<1, 512>>>(out);
}